// round 5
// baseline (speedup 1.0000x reference)
#include <cuda_runtime.h>
#include <cuda_bf16.h>
#include <math.h>
#include <float.h>

// ---------------- problem constants (fixed dataset) ----------------
#define NPTS    20000
#define PD      64          // point feature dim
#define GD      256         // grid feature dim
#define HH      96
#define WW      96
#define G       (HH*WW)     // 9216 grid points
#define KNN     32
#define HID     64
#define NC      64          // bin grid 64x64
#define NCELLS  (NC*NC)
#define CAP     1024        // candidate capacity per grid point
#define EPSLN   1e-5f

// step = f32(1/95), exactly as JAX f32 linspace computes it
#define STEP    (1.0f/95.0f)

// ---------------- scratch (device globals, no allocations) ----------------
__device__ float  g_pf[NPTS*GD];       // projected point features (20.5 MB)
__device__ int    g_start[NCELLS+1];
__device__ float4 g_pts[NPTS];         // (px, py, p2, idx-as-float), binned order
__device__ int    g_knn[G*KNN];
__device__ float  g_mid[G*GD];         // aggregated features before out-proj

// exact-rounding helpers for the KNN distance path (must bit-match reference)
__device__ __forceinline__ float grid_coord(int i) {
    return __fmul_rn((float)i, STEP);
}
__device__ __forceinline__ float sum_sq(float x, float y) {
    return __fadd_rn(__fmul_rn(x, x), __fmul_rn(y, y));
}
__device__ __forceinline__ float dot_ref(float gx, float gy, float px, float py) {
    return __fadd_rn(__fmul_rn(gx, px), __fmul_rn(gy, py));
}
__device__ __forceinline__ float dist2_ref(float g2, float m, float p2) {
    return __fadd_rn(__fsub_rn(g2, __fmul_rn(2.0f, m)), p2);
}
__device__ __forceinline__ int cell_of(float px, float py) {
    int cx = (int)(px * NC); cx = min(max(cx, 0), NC-1);
    int cy = (int)(py * NC); cy = min(max(cy, 0), NC-1);
    return cy * NC + cx;
}

// ======================================================================
// Kernel 1: pf = feat @ W_feat^T + b_feat   [20000 x 256]
// 32 rows x 256 cols per block; 256 threads; thread tile 8 rows x 4 cols.
// Inner iteration: 3x LDS.128 + 32 FMA. Accumulation kk-ascending
// (bit-identical to a plain sequential dot).
// ======================================================================
__global__ __launch_bounds__(256) void pf_kernel(
    const float* __restrict__ feat,   // [NPTS,64]
    const float* __restrict__ Wf,     // [256,64]
    const float* __restrict__ bf)     // [256]
{
    __shared__ __align__(16) float sW[32*260];   // [kk][c]
    __shared__ __align__(16) float sF[32*36];    // [kk][r]
    const int t    = threadIdx.x;
    const int row0 = blockIdx.x * 32;
    const int ty   = t >> 6;           // 0..3 -> r0 = ty*8
    const int tx   = t & 63;           // c0 = tx*4
    const int r0   = ty * 8;
    const int c0   = tx * 4;

    const float4* feat4 = (const float4*)feat;   // row stride 16
    const float4* Wf4   = (const float4*)Wf;     // row stride 16

    float4 acc[8];
#pragma unroll
    for (int r = 0; r < 8; r++) acc[r] = make_float4(0.f,0.f,0.f,0.f);

    for (int kt = 0; kt < PD; kt += 32) {
        // load W tile: 8192 floats = 2048 float4; 8 per thread
#pragma unroll
        for (int i = 0; i < 8; i++) {
            int lin = i * 256 + t;          // 0..2047
            int kk4 = lin & 7;              // kk = kk4*4
            int c   = lin >> 3;             // 0..255
            float4 v = Wf4[c*16 + (kt>>2) + kk4];
            sW[(kk4*4+0)*260 + c] = v.x;
            sW[(kk4*4+1)*260 + c] = v.y;
            sW[(kk4*4+2)*260 + c] = v.z;
            sW[(kk4*4+3)*260 + c] = v.w;
        }
        // load F tile: 1024 floats = 256 float4; 1 per thread
        {
            int kk4 = t & 7;
            int r   = t >> 3;               // 0..31
            float4 v = feat4[(size_t)(row0 + r)*16 + (kt>>2) + kk4];
            sF[(kk4*4+0)*36 + r] = v.x;
            sF[(kk4*4+1)*36 + r] = v.y;
            sF[(kk4*4+2)*36 + r] = v.z;
            sF[(kk4*4+3)*36 + r] = v.w;
        }
        __syncthreads();
#pragma unroll
        for (int kk = 0; kk < 32; kk++) {
            float4 w  = *(const float4*)&sW[kk*260 + c0];
            float4 fA = *(const float4*)&sF[kk*36 + r0];
            float4 fB = *(const float4*)&sF[kk*36 + r0 + 4];
            acc[0].x = fmaf(fA.x, w.x, acc[0].x); acc[0].y = fmaf(fA.x, w.y, acc[0].y);
            acc[0].z = fmaf(fA.x, w.z, acc[0].z); acc[0].w = fmaf(fA.x, w.w, acc[0].w);
            acc[1].x = fmaf(fA.y, w.x, acc[1].x); acc[1].y = fmaf(fA.y, w.y, acc[1].y);
            acc[1].z = fmaf(fA.y, w.z, acc[1].z); acc[1].w = fmaf(fA.y, w.w, acc[1].w);
            acc[2].x = fmaf(fA.z, w.x, acc[2].x); acc[2].y = fmaf(fA.z, w.y, acc[2].y);
            acc[2].z = fmaf(fA.z, w.z, acc[2].z); acc[2].w = fmaf(fA.z, w.w, acc[2].w);
            acc[3].x = fmaf(fA.w, w.x, acc[3].x); acc[3].y = fmaf(fA.w, w.y, acc[3].y);
            acc[3].z = fmaf(fA.w, w.z, acc[3].z); acc[3].w = fmaf(fA.w, w.w, acc[3].w);
            acc[4].x = fmaf(fB.x, w.x, acc[4].x); acc[4].y = fmaf(fB.x, w.y, acc[4].y);
            acc[4].z = fmaf(fB.x, w.z, acc[4].z); acc[4].w = fmaf(fB.x, w.w, acc[4].w);
            acc[5].x = fmaf(fB.y, w.x, acc[5].x); acc[5].y = fmaf(fB.y, w.y, acc[5].y);
            acc[5].z = fmaf(fB.y, w.z, acc[5].z); acc[5].w = fmaf(fB.y, w.w, acc[5].w);
            acc[6].x = fmaf(fB.z, w.x, acc[6].x); acc[6].y = fmaf(fB.z, w.y, acc[6].y);
            acc[6].z = fmaf(fB.z, w.z, acc[6].z); acc[6].w = fmaf(fB.z, w.w, acc[6].w);
            acc[7].x = fmaf(fB.w, w.x, acc[7].x); acc[7].y = fmaf(fB.w, w.y, acc[7].y);
            acc[7].z = fmaf(fB.w, w.z, acc[7].z); acc[7].w = fmaf(fB.w, w.w, acc[7].w);
        }
        __syncthreads();
    }
    float4 b4 = *(const float4*)&bf[c0];
    float4* out4 = (float4*)g_pf;
#pragma unroll
    for (int r = 0; r < 8; r++) {
        float4 v = acc[r];
        v.x += b4.x; v.y += b4.y; v.z += b4.z; v.w += b4.w;
        out4[(size_t)(row0 + r0 + r)*64 + tx] = v;
    }
}

// ======================================================================
// Fused binning: count -> scan -> scatter, ONE block, smem counters.
// ======================================================================
__global__ __launch_bounds__(1024) void bin_all_kernel(const float* __restrict__ pc)
{
    __shared__ int scnt[NCELLS];   // 16 KB
    __shared__ int wsum[32];
    const int t = threadIdx.x;
    const float2* __restrict__ pc2 = (const float2*)pc;

    for (int i = t; i < NCELLS; i += 1024) scnt[i] = 0;
    __syncthreads();

    for (int n = t; n < NPTS; n += 1024) {
        float2 p = pc2[n];
        atomicAdd(&scnt[cell_of(p.x, p.y)], 1);
    }
    __syncthreads();

    int v[4], s = 0;
#pragma unroll
    for (int i = 0; i < 4; i++) { v[i] = scnt[t*4 + i]; s += v[i]; }
    const int lane = t & 31, wid = t >> 5;
    int incl = s;
#pragma unroll
    for (int o = 1; o < 32; o <<= 1) {
        int u = __shfl_up_sync(0xffffffffu, incl, o);
        if (lane >= o) incl += u;
    }
    if (lane == 31) wsum[wid] = incl;
    __syncthreads();
    if (wid == 0) {
        int ws = wsum[lane];
#pragma unroll
        for (int o = 1; o < 32; o <<= 1) {
            int u = __shfl_up_sync(0xffffffffu, ws, o);
            if (lane >= o) ws += u;
        }
        wsum[lane] = ws;
    }
    __syncthreads();
    int run = (wid > 0 ? wsum[wid-1] : 0) + incl - s;
    int starts[4];
#pragma unroll
    for (int i = 0; i < 4; i++) {
        starts[i] = run;
        g_start[t*4 + i] = run;
        run += v[i];
    }
    if (t == 1023) g_start[NCELLS] = run;
    __syncthreads();
#pragma unroll
    for (int i = 0; i < 4; i++) scnt[t*4 + i] = starts[i];
    __syncthreads();

    for (int n = t; n < NPTS; n += 1024) {
        float2 p = pc2[n];
        int pos = atomicAdd(&scnt[cell_of(p.x, p.y)], 1);
        g_pts[pos] = make_float4(p.x, p.y, sum_sq(p.x, p.y), __int_as_float(n));
    }
}

// ======================================================================
// Kernel: exact KNN (K=32), one block (128 threads) per grid point.
// Bit-exact dist2; bitonic sort by (dist2, idx).  [R3-proven config]
// ======================================================================
__global__ __launch_bounds__(128) void knn_kernel()
{
    __shared__ float s_d[CAP];
    __shared__ int   s_i[CAP];
    __shared__ int   s_cnt;

    const int g   = blockIdx.x;
    const int tid = threadIdx.x;
    const int wx = g % WW, hy = g / WW;
    const float gx = grid_coord(wx), gy = grid_coord(hy);
    const float g2 = sum_sq(gx, gy);

    float R2 = 0.0015f;
    int cnt = 0;
    for (int iter = 0; iter < 24; iter++) {
        if (tid == 0) s_cnt = 0;
        __syncthreads();
        float R = sqrtf(R2);
        int cx0 = max(0,    (int)floorf((gx - R) * NC));
        int cx1 = min(NC-1, (int)floorf((gx + R) * NC));
        int cy0 = max(0,    (int)floorf((gy - R) * NC));
        int cy1 = min(NC-1, (int)floorf((gy + R) * NC));
        for (int cy = cy0; cy <= cy1; cy++) {
            int b = g_start[cy*NC + cx0];
            int e = g_start[cy*NC + cx1 + 1];
            for (int j = b + tid; j < e; j += 128) {
                float4 p = g_pts[j];
                float m = dot_ref(gx, gy, p.x, p.y);
                float d = dist2_ref(g2, m, p.z);
                if (d <= R2) {
                    int pos = atomicAdd(&s_cnt, 1);
                    if (pos < CAP) { s_d[pos] = d; s_i[pos] = __float_as_int(p.w); }
                }
            }
        }
        __syncthreads();
        cnt = s_cnt;
        if (cnt >= KNN && cnt <= CAP) break;
        R2 = (cnt < KNN) ? R2 * 2.0f : R2 * 0.5f;
        __syncthreads();
    }

    int M = KNN;
    while (M < cnt) M <<= 1;
    for (int j = cnt + tid; j < M; j += 128) { s_d[j] = FLT_MAX; s_i[j] = 0x7fffffff; }
    __syncthreads();

    for (int len = 2; len <= M; len <<= 1) {
        for (int stride = len >> 1; stride > 0; stride >>= 1) {
            for (int j = tid; j < (M >> 1); j += 128) {
                int i  = 2*j - (j & (stride - 1));
                int ip = i + stride;
                float d1 = s_d[i], d2 = s_d[ip];
                int   i1 = s_i[i], i2 = s_i[ip];
                bool up = ((i & len) == 0);
                bool gt = (d1 > d2) || (d1 == d2 && i1 > i2);
                bool lt = (d1 < d2) || (d1 == d2 && i1 < i2);
                if (up ? gt : lt) {
                    s_d[i] = d2; s_d[ip] = d1;
                    s_i[i] = i2; s_i[ip] = i1;
                }
            }
            __syncthreads();
        }
    }
    if (tid < KNN) g_knn[g*KNN + tid] = s_i[tid];
}

// ======================================================================
// Kernel: attention MLP + softmax + weighted feature gather
// One block (256 threads) per grid point. Vectorized gather (float4,
// 4-way k-split + smem reduce); MLP weights packed in float4.
// ======================================================================
__global__ __launch_bounds__(256) void attn_gather_kernel(
    const float* __restrict__ pc,
    const float* __restrict__ W1, const float* __restrict__ b1,
    const float* __restrict__ W2, const float* __restrict__ b2)
{
    __shared__ int    soff[KNN];           // row offsets into g_pf
    __shared__ float  sdx[KNN], sdy[KNN], sdd[KNN];
    __shared__ float  slog[KNN], swt[KNN];
    __shared__ __align__(16) float4 sW14[HID];   // (w0,w1,w2,b1)
    __shared__ float  sW2[HID];
    __shared__ __align__(16) float4 sRed[256];

    const int g = blockIdx.x;
    const int t = threadIdx.x;
    const int wx = g % WW, hy = g / WW;
    const float gx = grid_coord(wx), gy = grid_coord(hy);

    if (t < HID) {
        sW14[t] = make_float4(W1[t*3], W1[t*3+1], W1[t*3+2], b1[t]);
        sW2[t]  = W2[t];
    }
    if (t < KNN) {
        int id = g_knn[g*KNN + t];
        soff[t] = id * GD;
        float px = pc[2*id], py = pc[2*id+1];
        float dx = __fsub_rn(gx, px), dy = __fsub_rn(gy, py);
        sdx[t] = dx; sdy[t] = dy;
        sdd[t] = sqrtf(sum_sq(dx, dy));
    }
    __syncthreads();

    // MLP: thread t handles neighbor k = t/8, hidden slice of 8
    {
        int k  = t >> 3;
        int j0 = (t & 7) * 8;
        float dx = sdx[k], dy = sdy[k], dd = sdd[k];
        float acc = 0.0f;
#pragma unroll
        for (int jj = 0; jj < 8; jj++) {
            int j = j0 + jj;
            float4 w = sW14[j];
            float pre = fmaf(w.x, dx, fmaf(w.y, dy, fmaf(w.z, dd, w.w)));
            float ge  = 0.5f * pre * (1.0f + erff(pre * 0.70710678118654752f));
            acc = fmaf(sW2[j], ge, acc);
        }
#pragma unroll
        for (int o = 4; o >= 1; o >>= 1)
            acc += __shfl_down_sync(0xffffffffu, acc, o, 8);
        if ((t & 7) == 0) slog[k] = acc + b2[0];
    }
    __syncthreads();

    // softmax over 32 neighbors (warp 0)
    if (t < 32) {
        float l = slog[t];
        float m = l;
#pragma unroll
        for (int o = 16; o >= 1; o >>= 1) m = fmaxf(m, __shfl_xor_sync(0xffffffffu, m, o));
        float e = expf(l - m);
        float s = e;
#pragma unroll
        for (int o = 16; o >= 1; o >>= 1) s += __shfl_xor_sync(0xffffffffu, s, o);
        swt[t] = e / s;
    }
    __syncthreads();

    // gather: thread = (ksub = t>>6, colgrp = t&63); 8 neighbors each
    {
        const int cg   = t & 63;
        const int ksub = t >> 6;
        const float4* pf4 = (const float4*)g_pf;
        float4 a = make_float4(0.f,0.f,0.f,0.f);
#pragma unroll
        for (int j = 0; j < 8; j++) {
            int k = ksub * 8 + j;
            float w = swt[k];
            float4 v = pf4[(size_t)(soff[k] >> 2) + cg];
            a.x = fmaf(w, v.x, a.x);
            a.y = fmaf(w, v.y, a.y);
            a.z = fmaf(w, v.z, a.z);
            a.w = fmaf(w, v.w, a.w);
        }
        sRed[t] = a;
    }
    __syncthreads();
    if (t < 64) {
        float4 a = sRed[t], b = sRed[t+64], c = sRed[t+128], d = sRed[t+192];
        a.x = ((a.x + b.x) + c.x) + d.x;
        a.y = ((a.y + b.y) + c.y) + d.y;
        a.z = ((a.z + b.z) + c.z) + d.z;
        a.w = ((a.w + b.w) + c.w) + d.w;
        ((float4*)g_mid)[(size_t)g*64 + t] = a;
    }
}

// ======================================================================
// Kernel: out = mid @ W_out^T + b_out, then LayerNorm.
// 32 rows x 256 cols per block; thread tile 8r x 4c; LDS.128 inner loop.
// ======================================================================
__global__ __launch_bounds__(256) void outproj_ln_kernel(
    const float* __restrict__ Wo,   // [256,256]
    const float* __restrict__ bo,
    const float* __restrict__ lng,
    const float* __restrict__ lnb,
    float* __restrict__ out)
{
    __shared__ __align__(16) float sW[32*260];   // [kk][c]; reused as sOut [r][c]
    __shared__ __align__(16) float sF[32*36];    // [kk][r]
    __shared__ float sMu[32], sRs[32];

    const int t    = threadIdx.x;
    const int row0 = blockIdx.x * 32;
    const int ty   = t >> 6;
    const int tx   = t & 63;
    const int r0   = ty * 8;
    const int c0   = tx * 4;

    const float4* Wo4  = (const float4*)Wo;    // row stride 64
    const float4* mid4 = (const float4*)g_mid; // row stride 64

    float4 acc[8];
#pragma unroll
    for (int r = 0; r < 8; r++) acc[r] = make_float4(0.f,0.f,0.f,0.f);

    for (int kt = 0; kt < GD; kt += 32) {
#pragma unroll
        for (int i = 0; i < 8; i++) {
            int lin = i * 256 + t;
            int kk4 = lin & 7;
            int c   = lin >> 3;
            float4 v = Wo4[c*64 + (kt>>2) + kk4];
            sW[(kk4*4+0)*260 + c] = v.x;
            sW[(kk4*4+1)*260 + c] = v.y;
            sW[(kk4*4+2)*260 + c] = v.z;
            sW[(kk4*4+3)*260 + c] = v.w;
        }
        {
            int kk4 = t & 7;
            int r   = t >> 3;
            float4 v = mid4[(size_t)(row0 + r)*64 + (kt>>2) + kk4];
            sF[(kk4*4+0)*36 + r] = v.x;
            sF[(kk4*4+1)*36 + r] = v.y;
            sF[(kk4*4+2)*36 + r] = v.z;
            sF[(kk4*4+3)*36 + r] = v.w;
        }
        __syncthreads();
#pragma unroll
        for (int kk = 0; kk < 32; kk++) {
            float4 w  = *(const float4*)&sW[kk*260 + c0];
            float4 fA = *(const float4*)&sF[kk*36 + r0];
            float4 fB = *(const float4*)&sF[kk*36 + r0 + 4];
            acc[0].x = fmaf(fA.x, w.x, acc[0].x); acc[0].y = fmaf(fA.x, w.y, acc[0].y);
            acc[0].z = fmaf(fA.x, w.z, acc[0].z); acc[0].w = fmaf(fA.x, w.w, acc[0].w);
            acc[1].x = fmaf(fA.y, w.x, acc[1].x); acc[1].y = fmaf(fA.y, w.y, acc[1].y);
            acc[1].z = fmaf(fA.y, w.z, acc[1].z); acc[1].w = fmaf(fA.y, w.w, acc[1].w);
            acc[2].x = fmaf(fA.z, w.x, acc[2].x); acc[2].y = fmaf(fA.z, w.y, acc[2].y);
            acc[2].z = fmaf(fA.z, w.z, acc[2].z); acc[2].w = fmaf(fA.z, w.w, acc[2].w);
            acc[3].x = fmaf(fA.w, w.x, acc[3].x); acc[3].y = fmaf(fA.w, w.y, acc[3].y);
            acc[3].z = fmaf(fA.w, w.z, acc[3].z); acc[3].w = fmaf(fA.w, w.w, acc[3].w);
            acc[4].x = fmaf(fB.x, w.x, acc[4].x); acc[4].y = fmaf(fB.x, w.y, acc[4].y);
            acc[4].z = fmaf(fB.x, w.z, acc[4].z); acc[4].w = fmaf(fB.x, w.w, acc[4].w);
            acc[5].x = fmaf(fB.y, w.x, acc[5].x); acc[5].y = fmaf(fB.y, w.y, acc[5].y);
            acc[5].z = fmaf(fB.y, w.z, acc[5].z); acc[5].w = fmaf(fB.y, w.w, acc[5].w);
            acc[6].x = fmaf(fB.z, w.x, acc[6].x); acc[6].y = fmaf(fB.z, w.y, acc[6].y);
            acc[6].z = fmaf(fB.z, w.z, acc[6].z); acc[6].w = fmaf(fB.z, w.w, acc[6].w);
            acc[7].x = fmaf(fB.w, w.x, acc[7].x); acc[7].y = fmaf(fB.w, w.y, acc[7].y);
            acc[7].z = fmaf(fB.w, w.z, acc[7].z); acc[7].w = fmaf(fB.w, w.w, acc[7].w);
        }
        __syncthreads();
    }

    // stage rows (+bias) into sW reused as sOut [r][260]
    float4 b4 = *(const float4*)&bo[c0];
#pragma unroll
    for (int r = 0; r < 8; r++) {
        float4 v = acc[r];
        v.x += b4.x; v.y += b4.y; v.z += b4.z; v.w += b4.w;
        *(float4*)&sW[(r0 + r)*260 + c0] = v;
    }
    __syncthreads();

    // per-row mean/var (8 warps x 4 rows)
    const int lane = t & 31, wid = t >> 5;
    for (int r = wid; r < 32; r += 8) {
        float s = 0.0f;
#pragma unroll
        for (int i = lane; i < GD; i += 32) s += sW[r*260 + i];
#pragma unroll
        for (int o = 16; o >= 1; o >>= 1) s += __shfl_xor_sync(0xffffffffu, s, o);
        float mu = s * (1.0f / GD);
        float v = 0.0f;
#pragma unroll
        for (int i = lane; i < GD; i += 32) {
            float d = sW[r*260 + i] - mu;
            v = fmaf(d, d, v);
        }
#pragma unroll
        for (int o = 16; o >= 1; o >>= 1) v += __shfl_xor_sync(0xffffffffu, v, o);
        if (lane == 0) { sMu[r] = mu; sRs[r] = rsqrtf(v * (1.0f / GD) + EPSLN); }
    }
    __syncthreads();

    float4 g4 = *(const float4*)&lng[c0];
    float4 be4 = *(const float4*)&lnb[c0];
    float4* out4 = (float4*)out;
#pragma unroll
    for (int r = 0; r < 8; r++) {
        int rr = r0 + r;
        float mu = sMu[rr], rs = sRs[rr];
        float4 v = *(const float4*)&sW[rr*260 + c0];
        v.x = (v.x - mu) * rs * g4.x + be4.x;
        v.y = (v.y - mu) * rs * g4.y + be4.y;
        v.z = (v.z - mu) * rs * g4.z + be4.z;
        v.w = (v.w - mu) * rs * g4.w + be4.w;
        out4[(size_t)(row0 + rr)*64 + tx] = v;
    }
}

// ======================================================================
// launcher
// ======================================================================
extern "C" void kernel_launch(void* const* d_in, const int* in_sizes, int n_in,
                              void* d_out, int out_size)
{
    const float* point_features = (const float*)d_in[0];
    const float* point_coords   = (const float*)d_in[1];
    const float* W_feat         = (const float*)d_in[2];
    const float* b_feat         = (const float*)d_in[3];
    const float* W1             = (const float*)d_in[4];
    const float* b1             = (const float*)d_in[5];
    const float* W2             = (const float*)d_in[6];
    const float* b2             = (const float*)d_in[7];
    const float* W_out          = (const float*)d_in[8];
    const float* b_out          = (const float*)d_in[9];
    const float* ln_g           = (const float*)d_in[10];
    const float* ln_b           = (const float*)d_in[11];
    float* out = (float*)d_out;

    // 1. fused binning
    bin_all_kernel<<<1, 1024>>>(point_coords);

    // 2. feature projection
    pf_kernel<<<NPTS/32, 256>>>(point_features, W_feat, b_feat);

    // 3. exact KNN
    knn_kernel<<<G, 128>>>();

    // 4. attention + gather
    attn_gather_kernel<<<G, 256>>>(point_coords, W1, b1, W2, b2);

    // 5. output projection + layernorm
    outproj_ln_kernel<<<G/32, 256>>>(W_out, b_out, ln_g, ln_b, out);
}